// round 6
// baseline (speedup 1.0000x reference)
#include <cuda_runtime.h>
#include <math.h>

#define NN 1024
#define DD 64
#define DPP 32

// ---------------- scratch (device globals) ---------------------------------
__device__ float2   g_d2[NN * NN];        // 8 MB: (dH, dP) pairwise, full mirrored
__device__ unsigned g_mask [NN * 32];     // row-major top-K bitset (fully overwritten)
__device__ unsigned g_maskT[NN * 32];     // transposed bitset (atomicOr; zeroed in k_xy)
__device__ float    g_x[NN * DD];         // XX @ weight
__device__ float    g_y[NN * DD];         // x @ psi_w^T
__device__ int      g_c[NN];              // degree c[j]
__device__ int      g_diag[NN];           // A[j,j]
__device__ unsigned g_mxH, g_mxP;         // float bits (dists >= 0; min is exactly 0)
__device__ float    g_mu[DD], g_istd[DD];
__device__ unsigned g_arrive;             // last-block arrival counter (zeroed in k_xy)

// ---------------- 1. x = XX@W ; y = x@psi_w^T  (+ init) --------------------
__global__ void k_xy(const float* __restrict__ XX, const float* __restrict__ W,
                     const float* __restrict__ PW) {
    // init section (runs before k_dist/k_topk by stream order)
    int gt = blockIdx.x * 256 + threadIdx.x;     // 16384 threads
    g_maskT[gt * 2]     = 0u;
    g_maskT[gt * 2 + 1] = 0u;
    if (gt == 0) { g_mxH = 0u; g_mxP = 0u; g_arrive = 0u; }

    __shared__ float sW[64 * 64];     // sW[k*64+d]
    __shared__ float sPW[64 * 65];    // sPW[d*65+k] (padded)
    __shared__ float sXX[16 * 64];
    __shared__ float sx[16 * 64];
    int t = threadIdx.x;
    int row0 = blockIdx.x * 16;

    for (int idx = t; idx < 4096; idx += 256) sW[idx] = W[idx];
    for (int idx = t; idx < 4096; idx += 256) {
        int d = idx >> 6, k = idx & 63;
        sPW[d * 65 + k] = PW[idx];
    }
    for (int idx = t; idx < 1024; idx += 256) sXX[idx] = XX[row0 * 64 + idx];
    __syncthreads();

    int d = t & 63, rg = t >> 6;
    float acc[4] = {0.f, 0.f, 0.f, 0.f};
    #pragma unroll
    for (int k = 0; k < 64; ++k) {
        float wv = sW[k * 64 + d];
        #pragma unroll
        for (int rr = 0; rr < 4; ++rr) acc[rr] += sXX[(rg * 4 + rr) * 64 + k] * wv;
    }
    #pragma unroll
    for (int rr = 0; rr < 4; ++rr) {
        sx[(rg * 4 + rr) * 64 + d] = acc[rr];
        g_x[(row0 + rg * 4 + rr) * 64 + d] = acc[rr];
    }
    __syncthreads();

    float a2[4] = {0.f, 0.f, 0.f, 0.f};
    #pragma unroll
    for (int k = 0; k < 64; ++k) {
        float pw = sPW[d * 65 + k];
        #pragma unroll
        for (int rr = 0; rr < 4; ++rr) a2[rr] += sx[(rg * 4 + rr) * 64 + k] * pw;
    }
    #pragma unroll
    for (int rr = 0; rr < 4; ++rr) g_y[(row0 + rg * 4 + rr) * 64 + d] = a2[rr];
}

// ---------------- 2. distances: 64x64 tiles, 4x4 reg blocking, mirrored ----
__global__ void k_dist(const float* __restrict__ XH, const float* __restrict__ XP) {
    __shared__ float pool[64 * 66 * 2];   // 8448 floats = 33 KB, phase-aliased
    int t = threadIdx.x;

    // decode upper-triangle tile index (136 blocks over 16x16 tiles, by<=bx)
    int by = 0, rem = blockIdx.x;
    while (rem >= 16 - by) { rem -= 16 - by; ++by; }
    int bx = by + rem;
    int i0 = by * 64, j0 = bx * 64;
    int tx = t & 15, ty = t >> 4;
    const float sig = (float)(0.1 + 2.220446049250313e-16);  // sigma + float64 eps

    // phase 1: H features (64 dims)
    float (*sA)[65] = (float(*)[65])pool;
    float (*sB)[65] = (float(*)[65])(pool + 64 * 65);
    for (int idx = t; idx < 4096; idx += 256) {
        int r = idx >> 6, d = idx & 63;
        sA[r][d] = XH[(i0 + r) * 64 + d] / sig;
        sB[r][d] = XH[(j0 + r) * 64 + d] / sig;
    }
    __syncthreads();

    float accH[4][4];
    #pragma unroll
    for (int a = 0; a < 4; ++a)
        #pragma unroll
        for (int b = 0; b < 4; ++b) accH[a][b] = 0.f;
    #pragma unroll 8
    for (int d = 0; d < 64; ++d) {
        float rI[4], rJ[4];
        #pragma unroll
        for (int a = 0; a < 4; ++a) rI[a] = sA[ty + 16 * a][d];
        #pragma unroll
        for (int b = 0; b < 4; ++b) rJ[b] = sB[tx + 16 * b][d];
        #pragma unroll
        for (int a = 0; a < 4; ++a)
            #pragma unroll
            for (int b = 0; b < 4; ++b) {
                float df = rI[a] - rJ[b];
                accH[a][b] += df * df;
            }
    }
    __syncthreads();

    // phase 2: P features (32 dims), reuse pool
    float (*pA)[33] = (float(*)[33])pool;
    float (*pB)[33] = (float(*)[33])(pool + 64 * 33);
    for (int idx = t; idx < 2048; idx += 256) {
        int r = idx >> 5, p = idx & 31;
        pA[r][p] = XP[(i0 + r) * 32 + p];
        pB[r][p] = XP[(j0 + r) * 32 + p];
    }
    __syncthreads();

    float accP[4][4];
    #pragma unroll
    for (int a = 0; a < 4; ++a)
        #pragma unroll
        for (int b = 0; b < 4; ++b) accP[a][b] = 0.f;
    #pragma unroll 8
    for (int p = 0; p < 32; ++p) {
        float rI[4], rJ[4];
        #pragma unroll
        for (int a = 0; a < 4; ++a) rI[a] = pA[ty + 16 * a][p];
        #pragma unroll
        for (int b = 0; b < 4; ++b) rJ[b] = pB[tx + 16 * b][p];
        #pragma unroll
        for (int a = 0; a < 4; ++a)
            #pragma unroll
            for (int b = 0; b < 4; ++b) {
                float df = rI[a] - rJ[b];
                accP[a][b] += df * df;
            }
    }

    // phase 3: sqrt, straight write, max tracking
    float2 res[4][4];
    unsigned lmH = 0u, lmP = 0u;
    #pragma unroll
    for (int a = 0; a < 4; ++a)
        #pragma unroll
        for (int b = 0; b < 4; ++b) {
            float dh = sqrtf(accH[a][b]);
            float dp = sqrtf(accP[a][b]);
            res[a][b] = make_float2(dh, dp);
            lmH = max(lmH, __float_as_uint(dh));
            lmP = max(lmP, __float_as_uint(dp));
            g_d2[(i0 + ty + 16 * a) * NN + (j0 + tx + 16 * b)] = res[a][b];
        }
    lmH = __reduce_max_sync(0xffffffffu, lmH);
    lmP = __reduce_max_sync(0xffffffffu, lmP);
    if ((t & 31) == 0) { atomicMax(&g_mxH, lmH); atomicMax(&g_mxP, lmP); }

    // phase 4: mirror tile via shared transpose (coalesced both ways)
    if (bx != by) {
        __syncthreads();                              // done reading P smem
        float2 (*st)[66] = (float2(*)[66])pool;
        #pragma unroll
        for (int a = 0; a < 4; ++a)
            #pragma unroll
            for (int b = 0; b < 4; ++b)
                st[tx + 16 * b][ty + 16 * a] = res[a][b];
        __syncthreads();
        for (int idx = t; idx < 4096; idx += 256) {
            int r = idx >> 6, c = idx & 63;
            g_d2[(j0 + r) * NN + (i0 + c)] = st[r][c];
        }
    }
}

// ---------------- 3. fused WW + top-K; last block: deg + BN stats ----------
__global__ void k_topk(const int* __restrict__ Kp, const float* __restrict__ psi_b) {
    __shared__ int   sc[NN];            // degrees (tail phase)
    __shared__ float sred[8][64];       // bn cross-group reduce
    __shared__ int   slast;
    int t = threadIdx.x, lane = t & 31, w = t >> 5;
    int i = blockIdx.x * 8 + w;

    float mxH = __uint_as_float(g_mxH), mxP = __uint_as_float(g_mxP);
    float invH = 0.5f / mxH;              // min is exactly 0 (diagonal)
    float invP = 1.0f / mxP;

    // load row, compute WW keys (WW > 0 -> float bits are uint-ordered)
    unsigned key[32];
    #pragma unroll
    for (int s = 0; s < 32; ++s) {
        float2 dv = g_d2[i * NN + s * 32 + lane];
        float ww = expf(-dv.x * invH) + 0.2f * expf(-dv.y * invP);
        key[s] = __float_as_uint(ww);
    }

    int K = Kp ? Kp[0] : 16;
    if (K < 1) K = 1; if (K > NN) K = NN;

    unsigned mrow = 0u;                   // lane L accumulates mask word L
    for (int it = 0; it < K; ++it) {
        unsigned lm = 0u;
        #pragma unroll
        for (int s = 0; s < 32; ++s) lm = max(lm, key[s]);
        unsigned wm = __reduce_max_sync(0xffffffffu, lm);
        // lowest j holding wm (exact jax tie semantics)
        int jc = 0x7fffffff;
        #pragma unroll
        for (int s = 0; s < 32; ++s)
            if (key[s] == wm && s * 32 + lane < jc) jc = s * 32 + lane;
        int jmin = __reduce_min_sync(0xffffffffu, (unsigned)jc);
        // remove from owner lane; record bit
        if (lane == (jmin & 31)) key[jmin >> 5] = 0u;
        if (lane == (jmin >> 5)) mrow |= 1u << (jmin & 31);
        if (lane == 0)
            atomicOr(&g_maskT[jmin * 32 + (i >> 5)], 1u << (i & 31));
    }
    g_mask[i * 32 + lane] = mrow;

    // -------- last-block tail: degrees + closed-form BN stats --------------
    __syncthreads();
    if (t == 0) {
        __threadfence();
        unsigned old = atomicAdd(&g_arrive, 1u);
        slast = (old == gridDim.x - 1) ? 1 : 0;
    }
    __syncthreads();
    if (!slast) return;

    // degrees: warp w handles j = w, w+8, ... (lane = mask word), 4-way unroll
    for (int jb = 0; jb < NN; jb += 32) {
        int j0 = jb + w * 4;              // 4 consecutive j per warp per step
        unsigned m0 = g_mask[(j0 + 0) * 32 + lane] | g_maskT[(j0 + 0) * 32 + lane];
        unsigned m1 = g_mask[(j0 + 1) * 32 + lane] | g_maskT[(j0 + 1) * 32 + lane];
        unsigned m2 = g_mask[(j0 + 2) * 32 + lane] | g_maskT[(j0 + 2) * 32 + lane];
        unsigned m3 = g_mask[(j0 + 3) * 32 + lane] | g_maskT[(j0 + 3) * 32 + lane];
        int c0 = __reduce_add_sync(0xffffffffu, __popc(m0));
        int c1 = __reduce_add_sync(0xffffffffu, __popc(m1));
        int c2 = __reduce_add_sync(0xffffffffu, __popc(m2));
        int c3 = __reduce_add_sync(0xffffffffu, __popc(m3));
        int d0 = __shfl_sync(0xffffffffu, (int)((m0 >> ((j0+0) & 31)) & 1u), (j0+0) >> 5);
        int d1 = __shfl_sync(0xffffffffu, (int)((m1 >> ((j0+1) & 31)) & 1u), (j0+1) >> 5);
        int d2 = __shfl_sync(0xffffffffu, (int)((m2 >> ((j0+2) & 31)) & 1u), (j0+2) >> 5);
        int d3 = __shfl_sync(0xffffffffu, (int)((m3 >> ((j0+3) & 31)) & 1u), (j0+3) >> 5);
        if (lane == 0) {
            sc[j0] = c0; sc[j0+1] = c1; sc[j0+2] = c2; sc[j0+3] = c3;
            g_c[j0] = c0; g_c[j0+1] = c1; g_c[j0+2] = c2; g_c[j0+3] = c3;
            g_diag[j0] = d0; g_diag[j0+1] = d1; g_diag[j0+2] = d2; g_diag[j0+3] = d3;
        }
    }
    __syncthreads();

    // BN stats: thread t: d = t&63, group = t>>6 handles j = grp, grp+4, ...
    int d = t & 63, grp = t >> 6;
    float b = psi_b[d];
    float s1 = 0.f, s2 = 0.f;
    for (int j = grp; j < NN; j += 4) {
        float yv = g_y[j * DD + d];                 // coalesced across t
        float c  = (float)sc[j];
        s1 += yv * ((float)NN + c);
        float h1 = yv + b, h2 = 2.f * yv + b;
        s2 += ((float)NN - c) * h1 * h1 + c * h2 * h2;
    }
    sred[grp][d] = s1; sred[4 + grp][d] = s2;
    __syncthreads();
    if (t < 64) {
        float a1 = sred[0][t] + sred[1][t] + sred[2][t] + sred[3][t];
        float a2 = sred[4][t] + sred[5][t] + sred[6][t] + sred[7][t];
        const float invN2 = 1.0f / ((float)NN * (float)NN);
        float mu  = psi_b[t] + a1 * invN2;
        float var = a2 * invN2 - mu * mu;
        g_mu[t]   = mu;
        g_istd[t] = rsqrtf(var + 1e-5f);
    }
}

// ---------------- 4. final output (all three out segments) -----------------
__global__ void k_out(const float* __restrict__ psi_b, const float* __restrict__ gamma,
                      const float* __restrict__ beta, const float* __restrict__ bias,
                      const float* __restrict__ XP, float* __restrict__ out) {
    int idx = blockIdx.x * 256 + threadIdx.x;   // 65536 total
    int j = idx >> 6, d = idx & 63;
    float yv = g_y[idx], xv = g_x[idx];
    float z = (2.f * yv + psi_b[d] - g_mu[d]) * g_istd[d] * gamma[d] + beta[d];
    float s = 1.0f / (1.0f + expf(-z));
    float dg = (float)g_diag[j], c = (float)g_c[j];
    float val = xv * (dg + (c - dg) * s) + bias[d];
    out[idx] = val;                               // out[:, :DH] segment
    out[NN * DD + NN * DPP + idx] = val;          // full out segment
    if (idx < NN * DPP) out[NN * DD + idx] = XP[idx];  // XP passthrough
}

// ---------------- launch ----------------------------------------------------
extern "C" void kernel_launch(void* const* d_in, const int* in_sizes, int n_in,
                              void* d_out, int out_size) {
    // expected order: XH, XP, XX, K, weight, bias, psi_w, psi_b, gamma, beta
    int iXH = 0, iXP = 1, iXX = 2, iK = 3, iW = 4, iB = 5, iPW = 6, iPB = 7, iG = 8, iBe = 9;
    if (n_in == 9) {  // K dropped as a scalar
        iK = -1; iW = 3; iB = 4; iPW = 5; iPB = 6; iG = 7; iBe = 8;
    }
    const float* XH  = (const float*)d_in[iXH];
    const float* XP  = (const float*)d_in[iXP];
    const float* XX  = (const float*)d_in[iXX];
    const int*   Kp  = (iK >= 0) ? (const int*)d_in[iK] : nullptr;
    const float* W   = (const float*)d_in[iW];
    const float* B   = (const float*)d_in[iB];
    const float* PW  = (const float*)d_in[iPW];
    const float* PB  = (const float*)d_in[iPB];
    const float* G   = (const float*)d_in[iG];
    const float* Be  = (const float*)d_in[iBe];
    float* out = (float*)d_out;

    k_xy  <<<64, 256>>>(XX, W, PW);       // also zeroes maskT + arrival counter
    k_dist<<<136, 256>>>(XH, XP);
    k_topk<<<128, 256>>>(Kp, PB);         // tail: deg + BN stats
    k_out <<<256, 256>>>(PB, G, Be, B, XP, out);
    (void)in_sizes; (void)out_size;
}

// round 7
// speedup vs baseline: 1.5223x; 1.5223x over previous
#include <cuda_runtime.h>
#include <math.h>

#define NN 1024
#define DD 64
#define DPP 32

// ---------------- scratch (device globals) ---------------------------------
__device__ float2   g_d2[NN * NN];        // 8 MB: (dH, dP) pairwise, full mirrored
__device__ unsigned g_mask [NN * 32];     // row-major top-K bitset (fully overwritten)
__device__ unsigned g_maskT[NN * 32];     // transposed bitset (atomicOr; zeroed in k_xy)
__device__ float    g_x[NN * DD];         // XX @ weight
__device__ float    g_y[NN * DD];         // x @ psi_w^T
__device__ int      g_c[NN];              // degree c[j]
__device__ int      g_diag[NN];           // A[j,j]
__device__ unsigned g_mxH, g_mxP;         // float bits (dists >= 0; min is exactly 0)
__device__ float    g_bnp[16][2][DD];     // per-block BN partials (s1, s2)

// ---------------- 1. x = XX@W ; y = x@psi_w^T  (+ init) --------------------
__global__ void k_xy(const float* __restrict__ XX, const float* __restrict__ W,
                     const float* __restrict__ PW) {
    // init section (runs before k_dist/k_topk by stream order)
    int gt = blockIdx.x * 256 + threadIdx.x;     // 16384 threads
    g_maskT[gt * 2]     = 0u;
    g_maskT[gt * 2 + 1] = 0u;
    if (gt == 0) { g_mxH = 0u; g_mxP = 0u; }

    __shared__ float sW[64 * 64];     // sW[k*64+d]
    __shared__ float sPW[64 * 65];    // sPW[d*65+k] (padded)
    __shared__ float sXX[16 * 64];
    __shared__ float sx[16 * 64];
    int t = threadIdx.x;
    int row0 = blockIdx.x * 16;

    for (int idx = t; idx < 4096; idx += 256) sW[idx] = W[idx];
    for (int idx = t; idx < 4096; idx += 256) {
        int d = idx >> 6, k = idx & 63;
        sPW[d * 65 + k] = PW[idx];
    }
    for (int idx = t; idx < 1024; idx += 256) sXX[idx] = XX[row0 * 64 + idx];
    __syncthreads();

    int d = t & 63, rg = t >> 6;
    float acc[4] = {0.f, 0.f, 0.f, 0.f};
    #pragma unroll
    for (int k = 0; k < 64; ++k) {
        float wv = sW[k * 64 + d];
        #pragma unroll
        for (int rr = 0; rr < 4; ++rr) acc[rr] += sXX[(rg * 4 + rr) * 64 + k] * wv;
    }
    #pragma unroll
    for (int rr = 0; rr < 4; ++rr) {
        sx[(rg * 4 + rr) * 64 + d] = acc[rr];
        g_x[(row0 + rg * 4 + rr) * 64 + d] = acc[rr];
    }
    __syncthreads();

    float a2[4] = {0.f, 0.f, 0.f, 0.f};
    #pragma unroll
    for (int k = 0; k < 64; ++k) {
        float pw = sPW[d * 65 + k];
        #pragma unroll
        for (int rr = 0; rr < 4; ++rr) a2[rr] += sx[(rg * 4 + rr) * 64 + k] * pw;
    }
    #pragma unroll
    for (int rr = 0; rr < 4; ++rr) g_y[(row0 + rg * 4 + rr) * 64 + d] = a2[rr];
}

// ---------------- 2. distances: 64x64 tiles, 4x4 reg blocking, mirrored ----
__global__ void k_dist(const float* __restrict__ XH, const float* __restrict__ XP) {
    __shared__ float pool[64 * 66 * 2];   // 8448 floats = 33 KB, phase-aliased
    int t = threadIdx.x;

    // decode upper-triangle tile index (136 blocks over 16x16 tiles, by<=bx)
    int by = 0, rem = blockIdx.x;
    while (rem >= 16 - by) { rem -= 16 - by; ++by; }
    int bx = by + rem;
    int i0 = by * 64, j0 = bx * 64;
    int tx = t & 15, ty = t >> 4;
    const float sig = (float)(0.1 + 2.220446049250313e-16);  // sigma + float64 eps

    // phase 1: H features (64 dims)
    float (*sA)[65] = (float(*)[65])pool;
    float (*sB)[65] = (float(*)[65])(pool + 64 * 65);
    for (int idx = t; idx < 4096; idx += 256) {
        int r = idx >> 6, d = idx & 63;
        sA[r][d] = XH[(i0 + r) * 64 + d] / sig;
        sB[r][d] = XH[(j0 + r) * 64 + d] / sig;
    }
    __syncthreads();

    float accH[4][4];
    #pragma unroll
    for (int a = 0; a < 4; ++a)
        #pragma unroll
        for (int b = 0; b < 4; ++b) accH[a][b] = 0.f;
    #pragma unroll 8
    for (int d = 0; d < 64; ++d) {
        float rI[4], rJ[4];
        #pragma unroll
        for (int a = 0; a < 4; ++a) rI[a] = sA[ty + 16 * a][d];
        #pragma unroll
        for (int b = 0; b < 4; ++b) rJ[b] = sB[tx + 16 * b][d];
        #pragma unroll
        for (int a = 0; a < 4; ++a)
            #pragma unroll
            for (int b = 0; b < 4; ++b) {
                float df = rI[a] - rJ[b];
                accH[a][b] += df * df;
            }
    }
    __syncthreads();

    // phase 2: P features (32 dims), reuse pool
    float (*pA)[33] = (float(*)[33])pool;
    float (*pB)[33] = (float(*)[33])(pool + 64 * 33);
    for (int idx = t; idx < 2048; idx += 256) {
        int r = idx >> 5, p = idx & 31;
        pA[r][p] = XP[(i0 + r) * 32 + p];
        pB[r][p] = XP[(j0 + r) * 32 + p];
    }
    __syncthreads();

    float accP[4][4];
    #pragma unroll
    for (int a = 0; a < 4; ++a)
        #pragma unroll
        for (int b = 0; b < 4; ++b) accP[a][b] = 0.f;
    #pragma unroll 8
    for (int p = 0; p < 32; ++p) {
        float rI[4], rJ[4];
        #pragma unroll
        for (int a = 0; a < 4; ++a) rI[a] = pA[ty + 16 * a][p];
        #pragma unroll
        for (int b = 0; b < 4; ++b) rJ[b] = pB[tx + 16 * b][p];
        #pragma unroll
        for (int a = 0; a < 4; ++a)
            #pragma unroll
            for (int b = 0; b < 4; ++b) {
                float df = rI[a] - rJ[b];
                accP[a][b] += df * df;
            }
    }

    // phase 3: sqrt, straight write, max tracking
    float2 res[4][4];
    unsigned lmH = 0u, lmP = 0u;
    #pragma unroll
    for (int a = 0; a < 4; ++a)
        #pragma unroll
        for (int b = 0; b < 4; ++b) {
            float dh = sqrtf(accH[a][b]);
            float dp = sqrtf(accP[a][b]);
            res[a][b] = make_float2(dh, dp);
            lmH = max(lmH, __float_as_uint(dh));
            lmP = max(lmP, __float_as_uint(dp));
            g_d2[(i0 + ty + 16 * a) * NN + (j0 + tx + 16 * b)] = res[a][b];
        }
    lmH = __reduce_max_sync(0xffffffffu, lmH);
    lmP = __reduce_max_sync(0xffffffffu, lmP);
    if ((t & 31) == 0) { atomicMax(&g_mxH, lmH); atomicMax(&g_mxP, lmP); }

    // phase 4: mirror tile via shared transpose (coalesced both ways)
    if (bx != by) {
        __syncthreads();                              // done reading P smem
        float2 (*st)[66] = (float2(*)[66])pool;
        #pragma unroll
        for (int a = 0; a < 4; ++a)
            #pragma unroll
            for (int b = 0; b < 4; ++b)
                st[tx + 16 * b][ty + 16 * a] = res[a][b];
        __syncthreads();
        for (int idx = t; idx < 4096; idx += 256) {
            int r = idx >> 6, c = idx & 63;
            g_d2[(j0 + r) * NN + (i0 + c)] = st[r][c];
        }
    }
}

// ---------------- 3. fused WW + exact top-K (one warp per row) -------------
__global__ void k_topk(const int* __restrict__ Kp) {
    int t = threadIdx.x, lane = t & 31, w = t >> 5;
    int i = blockIdx.x * 8 + w;

    float mxH = __uint_as_float(g_mxH), mxP = __uint_as_float(g_mxP);
    float invH = 0.5f / mxH;              // min is exactly 0 (diagonal)
    float invP = 1.0f / mxP;

    // load row, compute WW keys (WW > 0 -> float bits are uint-ordered)
    unsigned key[32];
    #pragma unroll
    for (int s = 0; s < 32; ++s) {
        float2 dv = g_d2[i * NN + s * 32 + lane];
        float ww = expf(-dv.x * invH) + 0.2f * expf(-dv.y * invP);
        key[s] = __float_as_uint(ww);
    }

    int K = Kp ? Kp[0] : 16;
    if (K < 1) K = 1; if (K > NN) K = NN;

    unsigned mrow = 0u;                   // lane L accumulates mask word L
    for (int it = 0; it < K; ++it) {
        unsigned lm = 0u;
        #pragma unroll
        for (int s = 0; s < 32; ++s) lm = max(lm, key[s]);
        unsigned wm = __reduce_max_sync(0xffffffffu, lm);
        // lowest j holding wm (exact jax tie semantics)
        int jc = 0x7fffffff;
        #pragma unroll
        for (int s = 0; s < 32; ++s)
            if (key[s] == wm && s * 32 + lane < jc) jc = s * 32 + lane;
        int jmin = __reduce_min_sync(0xffffffffu, (unsigned)jc);
        // remove from owner lane WITHOUT dynamic register indexing (no spill)
        int ssel = jmin >> 5;
        if (lane == (jmin & 31)) {
            #pragma unroll
            for (int s = 0; s < 32; ++s)
                if (s == ssel) key[s] = 0u;
        }
        if (lane == ssel) mrow |= 1u << (jmin & 31);
        if (lane == 0)
            atomicOr(&g_maskT[jmin * 32 + (i >> 5)], 1u << (i & 31));
    }
    g_mask[i * 32 + lane] = mrow;
}

// ---------------- 4. degrees (own 64 j's) + BN partials, 16 blocks ---------
__global__ void k_bn1(const float* __restrict__ psi_b) {
    __shared__ int   sc[64];
    __shared__ float ss1[4][64], ss2[4][64];
    int t = threadIdx.x, lane = t & 31, w = t >> 5;
    int j0 = blockIdx.x * 64;

    // degrees for j in [j0, j0+64): warp w handles 8 j's
    for (int jj = 0; jj < 8; ++jj) {
        int j = j0 + w * 8 + jj;
        unsigned m = g_mask[j * 32 + lane] | g_maskT[j * 32 + lane];
        int c = __reduce_add_sync(0xffffffffu, __popc(m));
        int db = __shfl_sync(0xffffffffu, (int)((m >> (j & 31)) & 1u), j >> 5);
        if (lane == 0) {
            sc[j - j0] = c;
            g_c[j] = c;
            g_diag[j] = db;
        }
    }
    __syncthreads();

    // BN partials over this block's 64 rows (coalesced)
    int d = t & 63, rg = t >> 6;
    float b = psi_b[d];
    float s1 = 0.f, s2 = 0.f;
    for (int jb = 0; jb < 64; jb += 4) {
        int jl = jb + rg;
        float yv = g_y[(j0 + jl) * DD + d];
        float c  = (float)sc[jl];
        s1 += yv * ((float)NN + c);
        float h1 = yv + b, h2 = 2.f * yv + b;
        s2 += ((float)NN - c) * h1 * h1 + c * h2 * h2;
    }
    ss1[rg][d] = s1; ss2[rg][d] = s2;
    __syncthreads();
    if (rg == 0) {
        g_bnp[blockIdx.x][0][d] = ss1[0][d] + ss1[1][d] + ss1[2][d] + ss1[3][d];
        g_bnp[blockIdx.x][1][d] = ss2[0][d] + ss2[1][d] + ss2[2][d] + ss2[3][d];
    }
}

// ---------------- 5. final output (+ redundant per-block BN finalize) ------
__global__ void k_out(const float* __restrict__ psi_b, const float* __restrict__ gamma,
                      const float* __restrict__ beta, const float* __restrict__ bias,
                      const float* __restrict__ XP, float* __restrict__ out) {
    __shared__ float smu[64], sistd[64], sg[64], sb[64], sbi[64], spb[64];
    int t = threadIdx.x;
    if (t < 64) {
        float s1 = 0.f, s2 = 0.f;
        #pragma unroll
        for (int bl = 0; bl < 16; ++bl) {
            s1 += g_bnp[bl][0][t];
            s2 += g_bnp[bl][1][t];
        }
        const float invN2 = 1.0f / ((float)NN * (float)NN);
        float mu  = psi_b[t] + s1 * invN2;
        float var = s2 * invN2 - mu * mu;
        smu[t]   = mu;
        sistd[t] = rsqrtf(var + 1e-5f);
        sg[t] = gamma[t]; sb[t] = beta[t]; sbi[t] = bias[t]; spb[t] = psi_b[t];
    }
    __syncthreads();

    int q = blockIdx.x * 256 + t;               // 16384 float4 slots
    int j = q >> 4, d0 = (q & 15) * 4;
    float4 y4 = ((const float4*)g_y)[q];
    float4 x4 = ((const float4*)g_x)[q];
    float dg = (float)g_diag[j], c = (float)g_c[j];

    float yv[4] = {y4.x, y4.y, y4.z, y4.w};
    float xv[4] = {x4.x, x4.y, x4.z, x4.w};
    float4 o4;
    float* ov = (float*)&o4;
    #pragma unroll
    for (int u = 0; u < 4; ++u) {
        int d = d0 + u;
        float z = (2.f * yv[u] + spb[d] - smu[d]) * sistd[d] * sg[d] + sb[d];
        float s = 1.0f / (1.0f + expf(-z));
        ov[u] = xv[u] * (dg + (c - dg) * s) + sbi[d];
    }
    ((float4*)out)[q] = o4;                               // out[:, :DH] segment
    ((float4*)(out + NN * DD + NN * DPP))[q] = o4;        // full out segment
    if (q < NN * DPP / 4)
        ((float4*)(out + NN * DD))[q] = ((const float4*)XP)[q];  // XP passthrough
}

// ---------------- launch ----------------------------------------------------
extern "C" void kernel_launch(void* const* d_in, const int* in_sizes, int n_in,
                              void* d_out, int out_size) {
    // expected order: XH, XP, XX, K, weight, bias, psi_w, psi_b, gamma, beta
    int iXH = 0, iXP = 1, iXX = 2, iK = 3, iW = 4, iB = 5, iPW = 6, iPB = 7, iG = 8, iBe = 9;
    if (n_in == 9) {  // K dropped as a scalar
        iK = -1; iW = 3; iB = 4; iPW = 5; iPB = 6; iG = 7; iBe = 8;
    }
    const float* XH  = (const float*)d_in[iXH];
    const float* XP  = (const float*)d_in[iXP];
    const float* XX  = (const float*)d_in[iXX];
    const int*   Kp  = (iK >= 0) ? (const int*)d_in[iK] : nullptr;
    const float* W   = (const float*)d_in[iW];
    const float* B   = (const float*)d_in[iB];
    const float* PW  = (const float*)d_in[iPW];
    const float* PB  = (const float*)d_in[iPB];
    const float* G   = (const float*)d_in[iG];
    const float* Be  = (const float*)d_in[iBe];
    float* out = (float*)d_out;

    k_xy  <<<64, 256>>>(XX, W, PW);       // also zeroes maskT + resets maxes
    k_dist<<<136, 256>>>(XH, XP);
    k_topk<<<128, 256>>>(Kp);
    k_bn1 <<<16, 256>>>(PB);              // degrees + BN partials
    k_out <<<64, 256>>>(PB, G, Be, B, XP, out);
    (void)in_sizes; (void)out_size;
}

// round 8
// speedup vs baseline: 1.5309x; 1.0056x over previous
#include <cuda_runtime.h>
#include <math.h>

#define NN 1024
#define DD 64
#define DPP 32

// ---------------- scratch (device globals) ---------------------------------
__device__ float2   g_d2[NN * NN];        // 8 MB: (dH, dP) pairwise, full mirrored
__device__ unsigned g_mask [NN * 32];     // row-major top-K bitset (fully overwritten)
__device__ unsigned g_maskT[NN * 32];     // transposed bitset (atomicOr; zeroed in k_xy)
__device__ float    g_x[NN * DD];         // XX @ weight
__device__ float    g_y[NN * DD];         // x @ psi_w^T
__device__ int      g_c[NN];              // degree c[j]
__device__ int      g_diag[NN];           // A[j,j]
__device__ unsigned g_mxH, g_mxP;         // float bits (dists >= 0; min is exactly 0)
__device__ float    g_bnp[64][2][DD];     // per-block BN partials (s1, s2)

// ---------------- 1. x = XX@W ; y = x@psi_w^T  (+ init) --------------------
__global__ void k_xy(const float* __restrict__ XX, const float* __restrict__ W,
                     const float* __restrict__ PW) {
    // init section (runs before k_dist/k_topk by stream order)
    int gt = blockIdx.x * 256 + threadIdx.x;     // 16384 threads
    g_maskT[gt * 2]     = 0u;
    g_maskT[gt * 2 + 1] = 0u;
    if (gt == 0) { g_mxH = 0u; g_mxP = 0u; }

    __shared__ float sW[64 * 64];     // sW[k*64+d]
    __shared__ float sPW[64 * 65];    // sPW[d*65+k] (padded)
    __shared__ float sXX[16 * 64];
    __shared__ float sx[16 * 64];
    int t = threadIdx.x;
    int row0 = blockIdx.x * 16;

    for (int idx = t; idx < 4096; idx += 256) sW[idx] = W[idx];
    for (int idx = t; idx < 4096; idx += 256) {
        int d = idx >> 6, k = idx & 63;
        sPW[d * 65 + k] = PW[idx];
    }
    for (int idx = t; idx < 1024; idx += 256) sXX[idx] = XX[row0 * 64 + idx];
    __syncthreads();

    int d = t & 63, rg = t >> 6;
    float acc[4] = {0.f, 0.f, 0.f, 0.f};
    #pragma unroll
    for (int k = 0; k < 64; ++k) {
        float wv = sW[k * 64 + d];
        #pragma unroll
        for (int rr = 0; rr < 4; ++rr) acc[rr] += sXX[(rg * 4 + rr) * 64 + k] * wv;
    }
    #pragma unroll
    for (int rr = 0; rr < 4; ++rr) {
        sx[(rg * 4 + rr) * 64 + d] = acc[rr];
        g_x[(row0 + rg * 4 + rr) * 64 + d] = acc[rr];
    }
    __syncthreads();

    float a2[4] = {0.f, 0.f, 0.f, 0.f};
    #pragma unroll
    for (int k = 0; k < 64; ++k) {
        float pw = sPW[d * 65 + k];
        #pragma unroll
        for (int rr = 0; rr < 4; ++rr) a2[rr] += sx[(rg * 4 + rr) * 64 + k] * pw;
    }
    #pragma unroll
    for (int rr = 0; rr < 4; ++rr) g_y[(row0 + rg * 4 + rr) * 64 + d] = a2[rr];
}

// ---------------- 2. distances: 64x64 tiles, 4x4 reg blocking, mirrored ----
__global__ void k_dist(const float* __restrict__ XH, const float* __restrict__ XP) {
    __shared__ float pool[64 * 66 * 2];   // 8448 floats = 33 KB, phase-aliased
    int t = threadIdx.x;

    // decode upper-triangle tile index (136 blocks over 16x16 tiles, by<=bx)
    int by = 0, rem = blockIdx.x;
    while (rem >= 16 - by) { rem -= 16 - by; ++by; }
    int bx = by + rem;
    int i0 = by * 64, j0 = bx * 64;
    int tx = t & 15, ty = t >> 4;
    const float sig = (float)(0.1 + 2.220446049250313e-16);  // sigma + float64 eps

    // phase 1: H features (64 dims)
    float (*sA)[65] = (float(*)[65])pool;
    float (*sB)[65] = (float(*)[65])(pool + 64 * 65);
    for (int idx = t; idx < 4096; idx += 256) {
        int r = idx >> 6, d = idx & 63;
        sA[r][d] = XH[(i0 + r) * 64 + d] / sig;
        sB[r][d] = XH[(j0 + r) * 64 + d] / sig;
    }
    __syncthreads();

    float accH[4][4];
    #pragma unroll
    for (int a = 0; a < 4; ++a)
        #pragma unroll
        for (int b = 0; b < 4; ++b) accH[a][b] = 0.f;
    #pragma unroll 8
    for (int d = 0; d < 64; ++d) {
        float rI[4], rJ[4];
        #pragma unroll
        for (int a = 0; a < 4; ++a) rI[a] = sA[ty + 16 * a][d];
        #pragma unroll
        for (int b = 0; b < 4; ++b) rJ[b] = sB[tx + 16 * b][d];
        #pragma unroll
        for (int a = 0; a < 4; ++a)
            #pragma unroll
            for (int b = 0; b < 4; ++b) {
                float df = rI[a] - rJ[b];
                accH[a][b] += df * df;
            }
    }
    __syncthreads();

    // phase 2: P features (32 dims), reuse pool
    float (*pA)[33] = (float(*)[33])pool;
    float (*pB)[33] = (float(*)[33])(pool + 64 * 33);
    for (int idx = t; idx < 2048; idx += 256) {
        int r = idx >> 5, p = idx & 31;
        pA[r][p] = XP[(i0 + r) * 32 + p];
        pB[r][p] = XP[(j0 + r) * 32 + p];
    }
    __syncthreads();

    float accP[4][4];
    #pragma unroll
    for (int a = 0; a < 4; ++a)
        #pragma unroll
        for (int b = 0; b < 4; ++b) accP[a][b] = 0.f;
    #pragma unroll 8
    for (int p = 0; p < 32; ++p) {
        float rI[4], rJ[4];
        #pragma unroll
        for (int a = 0; a < 4; ++a) rI[a] = pA[ty + 16 * a][p];
        #pragma unroll
        for (int b = 0; b < 4; ++b) rJ[b] = pB[tx + 16 * b][p];
        #pragma unroll
        for (int a = 0; a < 4; ++a)
            #pragma unroll
            for (int b = 0; b < 4; ++b) {
                float df = rI[a] - rJ[b];
                accP[a][b] += df * df;
            }
    }

    // phase 3: sqrt, straight write, max tracking
    float2 res[4][4];
    unsigned lmH = 0u, lmP = 0u;
    #pragma unroll
    for (int a = 0; a < 4; ++a)
        #pragma unroll
        for (int b = 0; b < 4; ++b) {
            float dh = sqrtf(accH[a][b]);
            float dp = sqrtf(accP[a][b]);
            res[a][b] = make_float2(dh, dp);
            lmH = max(lmH, __float_as_uint(dh));
            lmP = max(lmP, __float_as_uint(dp));
            g_d2[(i0 + ty + 16 * a) * NN + (j0 + tx + 16 * b)] = res[a][b];
        }
    lmH = __reduce_max_sync(0xffffffffu, lmH);
    lmP = __reduce_max_sync(0xffffffffu, lmP);
    if ((t & 31) == 0) { atomicMax(&g_mxH, lmH); atomicMax(&g_mxP, lmP); }

    // phase 4: mirror tile via shared transpose (coalesced both ways)
    if (bx != by) {
        __syncthreads();                              // done reading P smem
        float2 (*st)[66] = (float2(*)[66])pool;
        #pragma unroll
        for (int a = 0; a < 4; ++a)
            #pragma unroll
            for (int b = 0; b < 4; ++b)
                st[tx + 16 * b][ty + 16 * a] = res[a][b];
        __syncthreads();
        for (int idx = t; idx < 4096; idx += 256) {
            int r = idx >> 6, c = idx & 63;
            g_d2[(j0 + r) * NN + (i0 + c)] = st[r][c];
        }
    }
}

// ---------------- 3. fused WW + exact top-K (one warp per row) -------------
__global__ void k_topk(const int* __restrict__ Kp) {
    int t = threadIdx.x, lane = t & 31, w = t >> 5;
    int i = blockIdx.x * 8 + w;

    float mxH = __uint_as_float(g_mxH), mxP = __uint_as_float(g_mxP);
    float invH = 0.5f / mxH;              // min is exactly 0 (diagonal)
    float invP = 1.0f / mxP;

    // load row, compute WW keys (WW > 0 -> float bits are uint-ordered)
    unsigned key[32];
    #pragma unroll
    for (int s = 0; s < 32; ++s) {
        float2 dv = g_d2[i * NN + s * 32 + lane];
        float ww = expf(-dv.x * invH) + 0.2f * expf(-dv.y * invP);
        key[s] = __float_as_uint(ww);
    }

    int K = Kp ? Kp[0] : 16;
    if (K < 1) K = 1; if (K > NN) K = NN;

    unsigned mrow = 0u;                   // lane L accumulates mask word L
    for (int it = 0; it < K; ++it) {
        unsigned lm = 0u;
        #pragma unroll
        for (int s = 0; s < 32; ++s) lm = max(lm, key[s]);
        unsigned wm = __reduce_max_sync(0xffffffffu, lm);
        // lowest j holding wm (exact jax tie semantics)
        int jc = 0x7fffffff;
        #pragma unroll
        for (int s = 0; s < 32; ++s)
            if (key[s] == wm && s * 32 + lane < jc) jc = s * 32 + lane;
        int jmin = __reduce_min_sync(0xffffffffu, (unsigned)jc);
        // remove from owner lane WITHOUT dynamic register indexing (no spill)
        int ssel = jmin >> 5;
        if (lane == (jmin & 31)) {
            #pragma unroll
            for (int s = 0; s < 32; ++s)
                if (s == ssel) key[s] = 0u;
        }
        if (lane == ssel) mrow |= 1u << (jmin & 31);
        if (lane == 0)
            atomicOr(&g_maskT[jmin * 32 + (i >> 5)], 1u << (i & 31));
    }
    g_mask[i * 32 + lane] = mrow;
}

// ---------------- 4. degrees (own 16 j's) + BN partials, 64 blocks ---------
__global__ void k_bn1(const float* __restrict__ psi_b) {
    __shared__ int   sc[16];
    __shared__ float ss1[4][64], ss2[4][64];
    int t = threadIdx.x, lane = t & 31, w = t >> 5;
    int j0 = blockIdx.x * 16;

    // degrees for j in [j0, j0+16): warp w handles 2 j's, loads issued together
    {
        int ja = j0 + w * 2, jb = ja + 1;
        unsigned ma = g_mask[ja * 32 + lane] | g_maskT[ja * 32 + lane];
        unsigned mb = g_mask[jb * 32 + lane] | g_maskT[jb * 32 + lane];
        int ca = __reduce_add_sync(0xffffffffu, __popc(ma));
        int cb = __reduce_add_sync(0xffffffffu, __popc(mb));
        int da = __shfl_sync(0xffffffffu, (int)((ma >> (ja & 31)) & 1u), ja >> 5);
        int db = __shfl_sync(0xffffffffu, (int)((mb >> (jb & 31)) & 1u), jb >> 5);
        if (lane == 0) {
            sc[ja - j0] = ca; sc[jb - j0] = cb;
            g_c[ja] = ca; g_c[jb] = cb;
            g_diag[ja] = da; g_diag[jb] = db;
        }
    }
    __syncthreads();

    // BN partials over this block's 16 rows: thread handles float4 of g_y
    int q = t;                            // 256 threads = 16 rows * 16 float4
    int jl = q >> 4, d0 = (q & 15) * 4;
    float4 y4 = ((const float4*)g_y)[j0 * 16 + q];
    float c = (float)sc[jl];
    float b0 = psi_b[d0], b1 = psi_b[d0 + 1], b2 = psi_b[d0 + 2], b3 = psi_b[d0 + 3];
    float s1v[4], s2v[4];
    {
        float yv[4] = {y4.x, y4.y, y4.z, y4.w};
        float bb[4] = {b0, b1, b2, b3};
        #pragma unroll
        for (int u = 0; u < 4; ++u) {
            s1v[u] = yv[u] * ((float)NN + c);
            float h1 = yv[u] + bb[u], h2 = 2.f * yv[u] + bb[u];
            s2v[u] = ((float)NN - c) * h1 * h1 + c * h2 * h2;
        }
    }
    // reduce across the 16 rows (jl) for each d: use shared, 4 groups of 4 rows
    int rg = jl & 3;                      // stripe rows into 4 groups
    // first, accumulate rows within group via shared atomics-free two-step:
    // write per-thread partials then tree-reduce over jl
    __shared__ float sp1[16][64], sp2[16][64];
    #pragma unroll
    for (int u = 0; u < 4; ++u) {
        sp1[jl][d0 + u] = s1v[u];
        sp2[jl][d0 + u] = s2v[u];
    }
    __syncthreads();
    // reduce 16 rows -> 4 (threads: rg = t>>6 handles rows rg, rg+4, rg+8, rg+12)
    int d = t & 63; rg = t >> 6;
    float a1 = sp1[rg][d] + sp1[rg + 4][d] + sp1[rg + 8][d] + sp1[rg + 12][d];
    float a2 = sp2[rg][d] + sp2[rg + 4][d] + sp2[rg + 8][d] + sp2[rg + 12][d];
    ss1[rg][d] = a1; ss2[rg][d] = a2;
    __syncthreads();
    if (rg == 0) {
        g_bnp[blockIdx.x][0][d] = ss1[0][d] + ss1[1][d] + ss1[2][d] + ss1[3][d];
        g_bnp[blockIdx.x][1][d] = ss2[0][d] + ss2[1][d] + ss2[2][d] + ss2[3][d];
    }
}

// ---------------- 5. final output (+ redundant per-block BN finalize) ------
__global__ void k_out(const float* __restrict__ psi_b, const float* __restrict__ gamma,
                      const float* __restrict__ beta, const float* __restrict__ bias,
                      const float* __restrict__ XP, float* __restrict__ out) {
    __shared__ float smu[64], sistd[64], sg[64], sb[64], sbi[64], spb[64];
    int t = threadIdx.x;
    if (t < 64) {
        float s1 = 0.f, s2 = 0.f;
        #pragma unroll 4
        for (int bl = 0; bl < 64; ++bl) {
            s1 += g_bnp[bl][0][t];
            s2 += g_bnp[bl][1][t];
        }
        const float invN2 = 1.0f / ((float)NN * (float)NN);
        float mu  = psi_b[t] + s1 * invN2;
        float var = s2 * invN2 - mu * mu;
        smu[t]   = mu;
        sistd[t] = rsqrtf(var + 1e-5f);
        sg[t] = gamma[t]; sb[t] = beta[t]; sbi[t] = bias[t]; spb[t] = psi_b[t];
    }
    __syncthreads();

    int q = blockIdx.x * 256 + t;               // 16384 float4 slots
    int j = q >> 4, d0 = (q & 15) * 4;
    float4 y4 = ((const float4*)g_y)[q];
    float4 x4 = ((const float4*)g_x)[q];
    float dg = (float)g_diag[j], c = (float)g_c[j];

    float yv[4] = {y4.x, y4.y, y4.z, y4.w};
    float xv[4] = {x4.x, x4.y, x4.z, x4.w};
    float4 o4;
    float* ov = (float*)&o4;
    #pragma unroll
    for (int u = 0; u < 4; ++u) {
        int d = d0 + u;
        float z = (2.f * yv[u] + spb[d] - smu[d]) * sistd[d] * sg[d] + sb[d];
        float s = 1.0f / (1.0f + expf(-z));
        ov[u] = xv[u] * (dg + (c - dg) * s) + sbi[d];
    }
    ((float4*)out)[q] = o4;                               // out[:, :DH] segment
    ((float4*)(out + NN * DD + NN * DPP))[q] = o4;        // full out segment
    if (q < NN * DPP / 4)
        ((float4*)(out + NN * DD))[q] = ((const float4*)XP)[q];  // XP passthrough
}

// ---------------- launch ----------------------------------------------------
extern "C" void kernel_launch(void* const* d_in, const int* in_sizes, int n_in,
                              void* d_out, int out_size) {
    // expected order: XH, XP, XX, K, weight, bias, psi_w, psi_b, gamma, beta
    int iXH = 0, iXP = 1, iXX = 2, iK = 3, iW = 4, iB = 5, iPW = 6, iPB = 7, iG = 8, iBe = 9;
    if (n_in == 9) {  // K dropped as a scalar
        iK = -1; iW = 3; iB = 4; iPW = 5; iPB = 6; iG = 7; iBe = 8;
    }
    const float* XH  = (const float*)d_in[iXH];
    const float* XP  = (const float*)d_in[iXP];
    const float* XX  = (const float*)d_in[iXX];
    const int*   Kp  = (iK >= 0) ? (const int*)d_in[iK] : nullptr;
    const float* W   = (const float*)d_in[iW];
    const float* B   = (const float*)d_in[iB];
    const float* PW  = (const float*)d_in[iPW];
    const float* PB  = (const float*)d_in[iPB];
    const float* G   = (const float*)d_in[iG];
    const float* Be  = (const float*)d_in[iBe];
    float* out = (float*)d_out;

    k_xy  <<<64, 256>>>(XX, W, PW);       // also zeroes maskT + resets maxes
    k_dist<<<136, 256>>>(XH, XP);
    k_topk<<<128, 256>>>(Kp);
    k_bn1 <<<64, 256>>>(PB);              // degrees + BN partials
    k_out <<<64, 256>>>(PB, G, Be, B, XP, out);
    (void)in_sizes; (void)out_size;
}

// round 9
// speedup vs baseline: 1.8680x; 1.2202x over previous
#include <cuda_runtime.h>
#include <math.h>

#define NN 1024
#define DD 64
#define DPP 32
#define NB_DIST 136
#define NB_BNOUT 64

// ---------------- scratch (device globals) ---------------------------------
__device__ float2   g_d2[NN * NN];        // 8 MB: (dH, dP) pairwise, full mirrored
__device__ unsigned g_mask [NN * 32];     // row-major top-K bitset (fully overwritten)
__device__ unsigned g_maskT[NN * 32];     // transposed bitset (atomicOr; zeroed in k_main)
__device__ float    g_x[NN * DD];         // XX @ weight
__device__ float    g_y[NN * DD];         // x @ psi_w^T
__device__ float2   g_bmx[NB_DIST];       // per-dist-block (maxH, maxP)
__device__ float    g_bnp[NB_BNOUT][2][DD];  // per-block BN partials (s1, s2)
__device__ unsigned g_arrive;             // bnout arrival counter (zeroed in k_main)

// ---------------- 1. merged: dist (blocks 0..135) + xy/init (136..199) -----
__global__ void k_main(const float* __restrict__ XH, const float* __restrict__ XP,
                       const float* __restrict__ XX, const float* __restrict__ W,
                       const float* __restrict__ PW) {
    __shared__ float pool[10304];         // 41.2 KB, phase-aliased
    __shared__ unsigned smx[8], smp[8];
    int t = threadIdx.x;

    if ((int)blockIdx.x >= NB_DIST) {
        // ---------------- xy body + init ----------------
        int xb = blockIdx.x - NB_DIST;    // 0..63
        int gt = xb * 256 + t;            // 16384 threads
        g_maskT[gt * 2]     = 0u;
        g_maskT[gt * 2 + 1] = 0u;
        if (gt == 0) g_arrive = 0u;

        float* sW  = pool;                // [k*64+d], 4096
        float* sPW = pool + 4096;         // [d*65+k], 4160 (padded)
        float* sXX = pool + 8256;         // 1024
        float* sx  = pool + 9280;         // 1024
        int row0 = xb * 16;

        for (int idx = t; idx < 4096; idx += 256) sW[idx] = W[idx];
        for (int idx = t; idx < 4096; idx += 256) {
            int d = idx >> 6, k = idx & 63;
            sPW[d * 65 + k] = PW[idx];
        }
        for (int idx = t; idx < 1024; idx += 256) sXX[idx] = XX[row0 * 64 + idx];
        __syncthreads();

        int d = t & 63, rg = t >> 6;
        float acc[4] = {0.f, 0.f, 0.f, 0.f};
        #pragma unroll
        for (int k = 0; k < 64; ++k) {
            float wv = sW[k * 64 + d];
            #pragma unroll
            for (int rr = 0; rr < 4; ++rr) acc[rr] += sXX[(rg * 4 + rr) * 64 + k] * wv;
        }
        #pragma unroll
        for (int rr = 0; rr < 4; ++rr) {
            sx[(rg * 4 + rr) * 64 + d] = acc[rr];
            g_x[(row0 + rg * 4 + rr) * 64 + d] = acc[rr];
        }
        __syncthreads();

        float a2[4] = {0.f, 0.f, 0.f, 0.f};
        #pragma unroll
        for (int k = 0; k < 64; ++k) {
            float pw = sPW[d * 65 + k];
            #pragma unroll
            for (int rr = 0; rr < 4; ++rr) a2[rr] += sx[(rg * 4 + rr) * 64 + k] * pw;
        }
        #pragma unroll
        for (int rr = 0; rr < 4; ++rr) g_y[(row0 + rg * 4 + rr) * 64 + d] = a2[rr];
        return;
    }

    // ---------------- dist body (upper-triangle 64x64 tiles, mirrored) -----
    int by = 0, rem = blockIdx.x;
    while (rem >= 16 - by) { rem -= 16 - by; ++by; }
    int bx = by + rem;
    int i0 = by * 64, j0 = bx * 64;
    int tx = t & 15, ty = t >> 4;
    const float sig = (float)(0.1 + 2.220446049250313e-16);  // sigma + float64 eps

    // phase 1: H features (64 dims)
    float (*sA)[65] = (float(*)[65])pool;
    float (*sB)[65] = (float(*)[65])(pool + 64 * 65);
    for (int idx = t; idx < 4096; idx += 256) {
        int r = idx >> 6, d = idx & 63;
        sA[r][d] = XH[(i0 + r) * 64 + d] / sig;
        sB[r][d] = XH[(j0 + r) * 64 + d] / sig;
    }
    __syncthreads();

    float accH[4][4];
    #pragma unroll
    for (int a = 0; a < 4; ++a)
        #pragma unroll
        for (int b = 0; b < 4; ++b) accH[a][b] = 0.f;
    #pragma unroll 8
    for (int d = 0; d < 64; ++d) {
        float rI[4], rJ[4];
        #pragma unroll
        for (int a = 0; a < 4; ++a) rI[a] = sA[ty + 16 * a][d];
        #pragma unroll
        for (int b = 0; b < 4; ++b) rJ[b] = sB[tx + 16 * b][d];
        #pragma unroll
        for (int a = 0; a < 4; ++a)
            #pragma unroll
            for (int b = 0; b < 4; ++b) {
                float df = rI[a] - rJ[b];
                accH[a][b] += df * df;
            }
    }
    __syncthreads();

    // phase 2: P features (32 dims), reuse pool
    float (*pA)[33] = (float(*)[33])pool;
    float (*pB)[33] = (float(*)[33])(pool + 64 * 33);
    for (int idx = t; idx < 2048; idx += 256) {
        int r = idx >> 5, p = idx & 31;
        pA[r][p] = XP[(i0 + r) * 32 + p];
        pB[r][p] = XP[(j0 + r) * 32 + p];
    }
    __syncthreads();

    float accP[4][4];
    #pragma unroll
    for (int a = 0; a < 4; ++a)
        #pragma unroll
        for (int b = 0; b < 4; ++b) accP[a][b] = 0.f;
    #pragma unroll 8
    for (int p = 0; p < 32; ++p) {
        float rI[4], rJ[4];
        #pragma unroll
        for (int a = 0; a < 4; ++a) rI[a] = pA[ty + 16 * a][p];
        #pragma unroll
        for (int b = 0; b < 4; ++b) rJ[b] = pB[tx + 16 * b][p];
        #pragma unroll
        for (int a = 0; a < 4; ++a)
            #pragma unroll
            for (int b = 0; b < 4; ++b) {
                float df = rI[a] - rJ[b];
                accP[a][b] += df * df;
            }
    }

    // phase 3: sqrt, straight write, per-block max
    float2 res[4][4];
    unsigned lmH = 0u, lmP = 0u;
    #pragma unroll
    for (int a = 0; a < 4; ++a)
        #pragma unroll
        for (int b = 0; b < 4; ++b) {
            float dh = sqrtf(accH[a][b]);
            float dp = sqrtf(accP[a][b]);
            res[a][b] = make_float2(dh, dp);
            lmH = max(lmH, __float_as_uint(dh));
            lmP = max(lmP, __float_as_uint(dp));
            g_d2[(i0 + ty + 16 * a) * NN + (j0 + tx + 16 * b)] = res[a][b];
        }
    lmH = __reduce_max_sync(0xffffffffu, lmH);
    lmP = __reduce_max_sync(0xffffffffu, lmP);
    if ((t & 31) == 0) { smx[t >> 5] = lmH; smp[t >> 5] = lmP; }
    __syncthreads();
    if (t == 0) {
        unsigned h = 0u, p = 0u;
        #pragma unroll
        for (int wv = 0; wv < 8; ++wv) { h = max(h, smx[wv]); p = max(p, smp[wv]); }
        g_bmx[blockIdx.x] = make_float2(__uint_as_float(h), __uint_as_float(p));
    }

    // phase 4: mirror tile via shared transpose (coalesced both ways)
    if (bx != by) {
        __syncthreads();                              // done reading P smem
        float2 (*st)[66] = (float2(*)[66])pool;
        #pragma unroll
        for (int a = 0; a < 4; ++a)
            #pragma unroll
            for (int b = 0; b < 4; ++b)
                st[tx + 16 * b][ty + 16 * a] = res[a][b];
        __syncthreads();
        for (int idx = t; idx < 4096; idx += 256) {
            int r = idx >> 6, c = idx & 63;
            g_d2[(j0 + r) * NN + (i0 + c)] = st[r][c];
        }
    }
}

// ---------------- 2. fused WW + exact top-K (one warp per row) -------------
__global__ void k_topk(const int* __restrict__ Kp) {
    __shared__ unsigned sredH[8], sredP[8];
    int t = threadIdx.x, lane = t & 31, w = t >> 5;
    int i = blockIdx.x * 8 + w;

    // reduce per-block maxes -> global max (prologue, ~300 cyc)
    {
        unsigned h = 0u, p = 0u;
        if (t < NB_DIST) {
            float2 v = g_bmx[t];
            h = __float_as_uint(v.x); p = __float_as_uint(v.y);
        }
        h = __reduce_max_sync(0xffffffffu, h);
        p = __reduce_max_sync(0xffffffffu, p);
        if (lane == 0) { sredH[w] = h; sredP[w] = p; }
    }
    __syncthreads();
    unsigned hh = 0u, pp = 0u;
    #pragma unroll
    for (int s = 0; s < 8; ++s) { hh = max(hh, sredH[s]); pp = max(pp, sredP[s]); }
    float invH = 0.5f / __uint_as_float(hh);   // min is exactly 0 (diagonal)
    float invP = 1.0f / __uint_as_float(pp);

    // load row, compute WW keys (WW > 0 -> float bits are uint-ordered)
    unsigned key[32];
    #pragma unroll
    for (int s = 0; s < 32; ++s) {
        float2 dv = g_d2[i * NN + s * 32 + lane];
        float ww = expf(-dv.x * invH) + 0.2f * expf(-dv.y * invP);
        key[s] = __float_as_uint(ww);
    }

    int K = Kp ? Kp[0] : 16;
    if (K < 1) K = 1; if (K > NN) K = NN;

    unsigned mrow = 0u;                   // lane L accumulates mask word L
    for (int it = 0; it < K; ++it) {
        unsigned lm = 0u;
        #pragma unroll
        for (int s = 0; s < 32; ++s) lm = max(lm, key[s]);
        unsigned wm = __reduce_max_sync(0xffffffffu, lm);
        // lowest j holding wm (exact jax tie semantics)
        int jc = 0x7fffffff;
        #pragma unroll
        for (int s = 0; s < 32; ++s)
            if (key[s] == wm && s * 32 + lane < jc) jc = s * 32 + lane;
        int jmin = __reduce_min_sync(0xffffffffu, (unsigned)jc);
        // remove from owner lane WITHOUT dynamic register indexing (no spill)
        int ssel = jmin >> 5;
        if (lane == (jmin & 31)) {
            #pragma unroll
            for (int s = 0; s < 32; ++s)
                if (s == ssel) key[s] = 0u;
        }
        if (lane == ssel) mrow |= 1u << (jmin & 31);
        if (lane == 0)
            atomicOr(&g_maskT[jmin * 32 + (i >> 5)], 1u << (i & 31));
    }
    g_mask[i * 32 + lane] = mrow;
}

// ---------------- 3. merged deg + BN + output (64 co-resident blocks) ------
__global__ void k_bnout(const float* __restrict__ psi_b, const float* __restrict__ gamma,
                        const float* __restrict__ beta, const float* __restrict__ bias,
                        const float* __restrict__ XP, float* __restrict__ out) {
    __shared__ int   sc[16], sdg[16];
    __shared__ float sp1[16][64], sp2[16][64];
    __shared__ float ss1[4][64], ss2[4][64];
    __shared__ float smu[64], sistd[64], sg[64], sb[64], sbi[64], spb[64];
    int t = threadIdx.x, lane = t & 31, w = t >> 5;
    int j0 = blockIdx.x * 16;

    // phase A: degrees + diag for own 16 j's (warp w: 2 j's, loads batched)
    {
        int ja = j0 + w * 2, jb = ja + 1;
        unsigned ma = g_mask[ja * 32 + lane] | g_maskT[ja * 32 + lane];
        unsigned mb = g_mask[jb * 32 + lane] | g_maskT[jb * 32 + lane];
        int ca = __reduce_add_sync(0xffffffffu, __popc(ma));
        int cb = __reduce_add_sync(0xffffffffu, __popc(mb));
        int da = __shfl_sync(0xffffffffu, (int)((ma >> (ja & 31)) & 1u), ja >> 5);
        int db = __shfl_sync(0xffffffffu, (int)((mb >> (jb & 31)) & 1u), jb >> 5);
        if (lane == 0) {
            sc[ja - j0] = ca; sc[jb - j0] = cb;
            sdg[ja - j0] = da; sdg[jb - j0] = db;
        }
    }
    __syncthreads();

    // phase B: BN partials over own 16 rows (float4 per thread)
    int q = blockIdx.x * 256 + t;         // global float4 slot; j = q>>4 in [j0, j0+16)
    int jl = t >> 4, d0 = (t & 15) * 4;
    float4 y4 = ((const float4*)g_y)[q];
    {
        float c = (float)sc[jl];
        float yv[4] = {y4.x, y4.y, y4.z, y4.w};
        #pragma unroll
        for (int u = 0; u < 4; ++u) {
            float bb = psi_b[d0 + u];
            sp1[jl][d0 + u] = yv[u] * ((float)NN + c);
            float h1 = yv[u] + bb, h2 = 2.f * yv[u] + bb;
            sp2[jl][d0 + u] = ((float)NN - c) * h1 * h1 + c * h2 * h2;
        }
    }
    __syncthreads();
    {
        int d = t & 63, rg = t >> 6;
        float a1 = sp1[rg][d] + sp1[rg + 4][d] + sp1[rg + 8][d] + sp1[rg + 12][d];
        float a2 = sp2[rg][d] + sp2[rg + 4][d] + sp2[rg + 8][d] + sp2[rg + 12][d];
        ss1[rg][d] = a1; ss2[rg][d] = a2;
    }
    __syncthreads();
    if (t < 64) {
        g_bnp[blockIdx.x][0][t] = ss1[0][t] + ss1[1][t] + ss1[2][t] + ss1[3][t];
        g_bnp[blockIdx.x][1][t] = ss2[0][t] + ss2[1][t] + ss2[2][t] + ss2[3][t];
    }
    __syncthreads();
    if (t == 0) {
        __threadfence();                  // release partials
        atomicAdd(&g_arrive, 1u);
        while (*(volatile unsigned*)&g_arrive < NB_BNOUT) { }   // all 64 co-resident
        __threadfence();                  // acquire partials
    }
    __syncthreads();

    // phase C: redundant parallel finalize (32 KB L2-hot per block)
    if (t < 64) {
        float s1 = 0.f, s2 = 0.f;
        #pragma unroll 4
        for (int bl = 0; bl < NB_BNOUT; ++bl) {
            s1 += g_bnp[bl][0][t];
            s2 += g_bnp[bl][1][t];
        }
        const float invN2 = 1.0f / ((float)NN * (float)NN);
        float mu  = psi_b[t] + s1 * invN2;
        float var = s2 * invN2 - mu * mu;
        smu[t]   = mu;
        sistd[t] = rsqrtf(var + 1e-5f);
        sg[t] = gamma[t]; sb[t] = beta[t]; sbi[t] = bias[t]; spb[t] = psi_b[t];
    }
    __syncthreads();

    // phase D: output slice (rows == own degree rows)
    float4 x4 = ((const float4*)g_x)[q];
    float dg = (float)sdg[jl], c = (float)sc[jl];
    float yv[4] = {y4.x, y4.y, y4.z, y4.w};
    float xv[4] = {x4.x, x4.y, x4.z, x4.w};
    float4 o4;
    float* ov = (float*)&o4;
    #pragma unroll
    for (int u = 0; u < 4; ++u) {
        int d = d0 + u;
        float z = (2.f * yv[u] + spb[d] - smu[d]) * sistd[d] * sg[d] + sb[d];
        float s = 1.0f / (1.0f + expf(-z));
        ov[u] = xv[u] * (dg + (c - dg) * s) + sbi[d];
    }
    ((float4*)out)[q] = o4;                               // out[:, :DH] segment
    ((float4*)(out + NN * DD + NN * DPP))[q] = o4;        // full out segment
    if (q < NN * DPP / 4)
        ((float4*)(out + NN * DD))[q] = ((const float4*)XP)[q];  // XP passthrough
}

// ---------------- launch ----------------------------------------------------
extern "C" void kernel_launch(void* const* d_in, const int* in_sizes, int n_in,
                              void* d_out, int out_size) {
    // expected order: XH, XP, XX, K, weight, bias, psi_w, psi_b, gamma, beta
    int iXH = 0, iXP = 1, iXX = 2, iK = 3, iW = 4, iB = 5, iPW = 6, iPB = 7, iG = 8, iBe = 9;
    if (n_in == 9) {  // K dropped as a scalar
        iK = -1; iW = 3; iB = 4; iPW = 5; iPB = 6; iG = 7; iBe = 8;
    }
    const float* XH  = (const float*)d_in[iXH];
    const float* XP  = (const float*)d_in[iXP];
    const float* XX  = (const float*)d_in[iXX];
    const int*   Kp  = (iK >= 0) ? (const int*)d_in[iK] : nullptr;
    const float* W   = (const float*)d_in[iW];
    const float* B   = (const float*)d_in[iB];
    const float* PW  = (const float*)d_in[iPW];
    const float* PB  = (const float*)d_in[iPB];
    const float* G   = (const float*)d_in[iG];
    const float* Be  = (const float*)d_in[iBe];
    float* out = (float*)d_out;

    k_main <<<NB_DIST + 64, 256>>>(XH, XP, XX, W, PW);
    k_topk <<<128, 256>>>(Kp);
    k_bnout<<<NB_BNOUT, 256>>>(PB, G, Be, B, XP, out);
    (void)in_sizes; (void)out_size;
}